// round 14
// baseline (speedup 1.0000x reference)
#include <cuda_runtime.h>

// SCCT_NGT: 5000-step explicit PDE loop on NX=64 with tiny MLP closure,
// then phi2 = mean(u^2) and histogram entropy H of |u|/max.
//
// One persistent CTA, 256 threads = 8 warps (2/SMSP). Thread t: point
// p = t>>2, sub = t&3 owns an 8-unit slice of the 32 hidden units; quad
// all-reduce via two __shfl_xor hops; lane sub==0 writes the point.
//
// R12 = R8's packed-FFMA2 math (measured -163us vs scalar via R8-R9
// subtraction) + R7's single-buffer/two-hop exchange (measured best).
// Split-store (R9, +300us) stays reverted.
// Pipe model: FMA-class was the binding pipe in R7 (~160 cyc/SMSP/step);
// fma.rn.f32x2 halves the z-chain FMA ops, pushing the floor back to the
// 128-cyc/SMSP MUFU window (16 warp-TANH @ rt 8).

#define NXc 64
#define HIDc 16
#define UPT 8   // hidden units per thread (4 f32x2 pairs)

typedef unsigned long long u64p;

__device__ __forceinline__ float tanhf_mufu(float x) {
    float y; asm("tanh.approx.f32 %0, %1;" : "=f"(y) : "f"(x)); return y;
}
__device__ __forceinline__ u64p pack2(float lo, float hi) {
    u64p r; asm("mov.b64 %0, {%1, %2};" : "=l"(r) : "f"(lo), "f"(hi)); return r;
}
__device__ __forceinline__ void unpack2(u64p v, float& lo, float& hi) {
    asm("mov.b64 {%0, %1}, %2;" : "=f"(lo), "=f"(hi) : "l"(v));
}
__device__ __forceinline__ u64p fma2(u64p a, u64p b, u64p c) {
    u64p r; asm("fma.rn.f32x2 %0, %1, %2, %3;" : "=l"(r) : "l"(a), "l"(b), "l"(c));
    return r;
}

__global__ __launch_bounds__(256, 1)
void scct_kernel(const float* __restrict__ u0,
                 const float* __restrict__ w1, const float* __restrict__ b1,
                 const float* __restrict__ w2, const float* __restrict__ b2,
                 const float* __restrict__ wc, const float* __restrict__ bc,
                 const float* __restrict__ gammap, const int* __restrict__ Ntp,
                 float* __restrict__ out)
{
    __shared__ float ubuf[2][NXc + 2];   // ghost cells at [0] and [NXc+1], always 0
    __shared__ float s2red[NXc];
    __shared__ float vmred[NXc];
    __shared__ int   hist[NXc];

    const int t   = threadIdx.x;
    const int p   = t >> 2;      // grid point 0..63
    const int sub = t & 3;       // 4 threads per point
    const float bmask = (p == 0 || p == NXc - 1) ? 0.0f : 1.0f;  // Dirichlet

    const float gamma = gammap[0];
    const int   Nt    = Ntp[0];
    const float bcv   = bc[0];

    const float DTf  = (float)1e-4;
    const float R2DX = 31.5f;     // 1/(2*DX), exact
    const float RDX2 = 3969.0f;   // 1/DX^2, exact

    // Masked per-thread update constants (zero on boundary threads -> un = 0).
    const float DTf_m  = DTf * bmask;
    const float DTg_m  = DTf * gamma * bmask;
    const float DTgb_m = DTf * gamma * bcv * bmask;
    const float K08R   = 0.8f * RDX2;        // core: (um+up) coeff
    const float C1     = 0.5f - 2.0f * K08R; // core: uc coeff

    // This thread's 8-unit weight slice, stencil pre-folded, packed in pairs:
    //   z_j = um*(RDX2*wq - R2DX*wb) + uc*(wa - 2*RDX2*wq)
    //       + up*(R2DX*wb + RDX2*wq) + bb
    const float* W  = (sub >> 1) ? w2 : w1;
    const float* Bp = (sub >> 1) ? b2 : b1;
    const int j0 = (sub & 1) * UPT;
    u64p AwP[UPT/2], BwP[UPT/2], CwP[UPT/2], bbP[UPT/2], cwP[UPT/2];
#pragma unroll
    for (int k = 0; k < UPT / 2; k++) {
        float A2[2], B2[2], C2[2], b2r[2], c2[2];
#pragma unroll
        for (int e = 0; e < 2; e++) {
            int j = j0 + 2 * k + e;
            float wa = W[j * 3 + 0];
            float wb = W[j * 3 + 1];
            float wq = W[j * 3 + 2];
            A2[e]  = RDX2 * wq - R2DX * wb;
            B2[e]  = wa - 2.0f * RDX2 * wq;
            C2[e]  = R2DX * wb + RDX2 * wq;
            b2r[e] = Bp[j];
            c2[e]  = wc[(sub >> 1) * HIDc + j];
        }
        AwP[k] = pack2(A2[0], A2[1]);
        BwP[k] = pack2(B2[0], B2[1]);
        CwP[k] = pack2(C2[0], C2[1]);
        bbP[k] = pack2(b2r[0], b2r[1]);
        cwP[k] = pack2(c2[0], c2[1]);
    }

    // Init shared buffers (ghosts zero in both buffers; never rewritten).
    if (t < NXc + 2) { ubuf[0][t] = 0.0f; ubuf[1][t] = 0.0f; }
    __syncthreads();
    if (t < NXc) ubuf[0][t + 1] = u0[t];
    __syncthreads();

    int cur = 0;
    for (int it = 0; it < Nt; ++it) {
        const float um = ubuf[cur][p];
        const float uc = ubuf[cur][p + 1];
        const float up = ubuf[cur][p + 2];

        // core = 0.8*lap + 0.5*uc - uc^3 = (um+up)*K08R + uc*(C1 - uc^2)
        const float q    = fmaf(-uc, uc, C1);
        const float core = fmaf(um + up, K08R, uc * q);
        const float base = fmaf(DTf_m, core, uc * bmask) + DTgb_m;

        const u64p umP = pack2(um, um);
        const u64p ucP = pack2(uc, uc);
        const u64p upP = pack2(up, up);

        u64p acc0 = pack2(0.0f, 0.0f);
        u64p acc1 = acc0;
#pragma unroll
        for (int k = 0; k < UPT / 2; k += 2) {
            u64p za = fma2(upP, CwP[k],   fma2(ucP, BwP[k],   fma2(umP, AwP[k],   bbP[k])));
            u64p zb = fma2(upP, CwP[k+1], fma2(ucP, BwP[k+1], fma2(umP, AwP[k+1], bbP[k+1])));
            float z0, z1, z2, z3;
            unpack2(za, z0, z1);
            unpack2(zb, z2, z3);
            u64p ta = pack2(tanhf_mufu(z0), tanhf_mufu(z1));
            u64p tb = pack2(tanhf_mufu(z2), tanhf_mufu(z3));
            acc0 = fma2(cwP[k],   ta, acc0);
            acc1 = fma2(cwP[k+1], tb, acc1);
        }
        float a0, a1, a2, a3;
        unpack2(acc0, a0, a1);
        unpack2(acc1, a2, a3);
        float s = (a0 + a1) + (a2 + a3);

        // Quad all-reduce: lanes {4q..4q+3} hold the 4 slices of point p.
        s += __shfl_xor_sync(0xffffffffu, s, 1);
        s += __shfl_xor_sync(0xffffffffu, s, 2);

        if (sub == 0) {
            ubuf[cur ^ 1][p + 1] = fmaf(DTg_m, s, base);
        }
        __syncthreads();
        cur ^= 1;
    }

    // ---- Final statistics ----
    const float* uf = &ubuf[cur][1];
    if (t < NXc) {
        float v = uf[t];
        out[t]     = v;
        s2red[t]   = v * v;
        vmred[t]   = fabsf(v);
        hist[t]    = 0;
    }
    __syncthreads();

    if (t == 0) {
        float s2 = 0.0f, vmax = 0.0f;
        for (int i = 0; i < NXc; i++) {
            s2   += s2red[i];
            vmax  = fmaxf(vmax, vmred[i]);
        }
        out[NXc] = s2 * (1.0f / 64.0f);   // phi2 = mean(u^2)

        const float vden = fmaxf(vmax, 1e-12f);
        for (int i = 0; i < NXc; i++) {
            float vn = vmred[i] / vden;   // in [0, 1]
            int b = (int)floorf(vn * 64.0f);
            if (b > 63) b = 63;
            if (b < 0)  b = 0;
            // Exact searchsorted(edges, vn, 'right'): edges k/64 exact in fp32.
            while (b > 0  && vn <  (float)b       * (1.0f / 64.0f)) b--;
            while (b < 63 && vn >= (float)(b + 1) * (1.0f / 64.0f)) b++;
            hist[b]++;
        }
        float H = 0.0f;
        for (int i = 0; i < NXc; i++) {
            float pb = (float)hist[i] * (1.0f / 64.0f);
            H -= pb * logf(pb + 1e-12f);
        }
        if (vmax < 1e-12f) H = 0.0f;
        out[NXc + 1] = H;
    }
}

extern "C" void kernel_launch(void* const* d_in, const int* in_sizes, int n_in,
                              void* d_out, int out_size) {
    const float* u0    = (const float*)d_in[0];
    const float* w1    = (const float*)d_in[1];
    const float* b1    = (const float*)d_in[2];
    const float* w2    = (const float*)d_in[3];
    const float* b2    = (const float*)d_in[4];
    const float* wc    = (const float*)d_in[5];
    const float* bc    = (const float*)d_in[6];
    const float* gamma = (const float*)d_in[7];
    const int*   Nt    = (const int*)d_in[8];
    float* out = (float*)d_out;

    scct_kernel<<<1, 256>>>(u0, w1, b1, w2, b2, wc, bc, gamma, Nt, out);
}

// round 16
// speedup vs baseline: 1.0731x; 1.0731x over previous
#include <cuda_runtime.h>

// SCCT_NGT: 5000-step explicit PDE loop on NX=64 with tiny MLP closure,
// then phi2 = mean(u^2) and histogram entropy H of |u|/max.
//
// One persistent CTA, 256 threads = 8 warps (2/SMSP). Thread t: point
// p = t>>2, sub = t&3 owns an 8-unit slice of the 32 hidden units.
//
// R15: single-hop reduce + branch-free interleaved split store.
// u is stored as float2 {M, P} (u = M + P). After one shfl_xor(1):
//   lanes sub in {0,1} hold sA (units 0..15), {2,3} hold sB (16..31).
// Lane 0 stores M = fmaf(DTg, sA, base); lane 2 stores P = DTg*sB —
// ONE predicated STS to fp[sub>>1], no divergent else (R9's mistakes:
// 6 scalar LDS to two arrays + if/else BSSY — both avoided here).
// Consumers read 3x LDS.64 and add pairs; only the um add (+4 cyc) is on
// the z critical path. Net vs R7: tail -26 (second hop), head +4.

#define NXc 64
#define HIDc 16
#define UPT 8   // hidden units per thread

__device__ __forceinline__ float tanhf_mufu(float x) {
    float y; asm("tanh.approx.f32 %0, %1;" : "=f"(y) : "f"(x)); return y;
}

__global__ __launch_bounds__(256, 1)
void scct_kernel(const float* __restrict__ u0,
                 const float* __restrict__ w1, const float* __restrict__ b1,
                 const float* __restrict__ w2, const float* __restrict__ b2,
                 const float* __restrict__ wc, const float* __restrict__ bc,
                 const float* __restrict__ gammap, const int* __restrict__ Ntp,
                 float* __restrict__ out)
{
    __shared__ float2 ubuf[2][NXc + 2];  // {M,P}; ghosts [0],[NXc+1] stay {0,0}
    __shared__ float s2red[NXc];
    __shared__ float vmred[NXc];
    __shared__ int   hist[NXc];

    const int t   = threadIdx.x;
    const int p   = t >> 2;      // grid point 0..63
    const int sub = t & 3;       // 4 threads per point
    const float bmask = (p == 0 || p == NXc - 1) ? 0.0f : 1.0f;  // Dirichlet
    const float bsel  = (sub == 0) ? 1.0f : 0.0f;  // base only in the M store

    const float gamma = gammap[0];
    const int   Nt    = Ntp[0];
    const float bcv   = bc[0];

    const float DTf  = (float)1e-4;
    const float R2DX = 31.5f;     // 1/(2*DX), exact
    const float RDX2 = 3969.0f;   // 1/DX^2, exact

    // Masked per-thread update constants (zero on boundary threads -> un = 0).
    const float DTf_m  = DTf * bmask;
    const float DTg_m  = DTf * gamma * bmask;
    const float DTgb_m = DTf * gamma * bcv * bmask;
    const float K08R   = 0.8f * RDX2;        // core: (um+up) coeff
    const float C1     = 0.5f - 2.0f * K08R; // core: uc coeff

    // This thread's 8-unit weight slice, stencil pre-folded:
    //   z_j = um*(RDX2*wq - R2DX*wb) + uc*(wa - 2*RDX2*wq)
    //       + up*(R2DX*wb + RDX2*wq) + bb
    const float* W  = (sub >> 1) ? w2 : w1;
    const float* Bp = (sub >> 1) ? b2 : b1;
    const int j0 = (sub & 1) * UPT;
    float Aw[UPT], Bw[UPT], Cw[UPT], bb[UPT], cwr[UPT];
#pragma unroll
    for (int k = 0; k < UPT; k++) {
        int j = j0 + k;
        float wa = W[j * 3 + 0];
        float wb = W[j * 3 + 1];
        float wq = W[j * 3 + 2];
        Aw[k]  = RDX2 * wq - R2DX * wb;
        Bw[k]  = wa - 2.0f * RDX2 * wq;
        Cw[k]  = R2DX * wb + RDX2 * wq;
        bb[k]  = Bp[j];
        cwr[k] = wc[(sub >> 1) * HIDc + j];
    }

    // Init shared buffers (ghosts zero in both buffers; never rewritten).
    if (t < NXc + 2) {
        ubuf[0][t] = make_float2(0.0f, 0.0f);
        ubuf[1][t] = make_float2(0.0f, 0.0f);
    }
    __syncthreads();
    if (t < NXc) ubuf[0][t + 1].x = u0[t];
    __syncthreads();

    float2* bufA = &ubuf[0][0];
    float2* bufB = &ubuf[1][0];

    for (int it = 0; it < Nt; ++it) {
        const float2 vm = bufA[p];
        const float2 vc = bufA[p + 1];
        const float2 vp = bufA[p + 2];
        const float um = vm.x + vm.y;
        const float uc = vc.x + vc.y;
        const float up = vp.x + vp.y;

        // core = 0.8*lap + 0.5*uc - uc^3 = (um+up)*K08R + uc*(C1 - uc^2)
        const float q    = fmaf(-uc, uc, C1);
        const float core = fmaf(um + up, K08R, uc * q);
        const float base = fmaf(DTf_m, core, uc * bmask) + DTgb_m;

        float s0 = 0.0f, s1 = 0.0f;
#pragma unroll
        for (int k = 0; k < UPT; k += 2) {
            float za = fmaf(up, Cw[k],   fmaf(uc, Bw[k],   fmaf(um, Aw[k],   bb[k])));
            float zb = fmaf(up, Cw[k+1], fmaf(uc, Bw[k+1], fmaf(um, Aw[k+1], bb[k+1])));
            float ta = tanhf_mufu(za);
            float tb = tanhf_mufu(zb);
            s0 = fmaf(cwr[k],   ta, s0);
            s1 = fmaf(cwr[k+1], tb, s1);
        }
        float s = s0 + s1;
        // ONE hop: lanes {0,1} -> sA (units 0..15), lanes {2,3} -> sB (16..31)
        s += __shfl_xor_sync(0xffffffffu, s, 1);

        // Branch-free split store: lane 0 -> M, lane 2 -> P (same float2 slot).
        const float val = fmaf(DTg_m, s, base * bsel);
        if ((sub & 1) == 0) {
            float* fp = reinterpret_cast<float*>(&bufB[p + 1]);
            fp[sub >> 1] = val;
        }
        __syncthreads();
        float2* tmp = bufA; bufA = bufB; bufB = tmp;
    }

    // ---- Final statistics ----
    if (t < NXc) {
        float2 vv = bufA[t + 1];
        float v = vv.x + vv.y;
        out[t]     = v;
        s2red[t]   = v * v;
        vmred[t]   = fabsf(v);
        hist[t]    = 0;
    }
    __syncthreads();

    if (t == 0) {
        float s2 = 0.0f, vmax = 0.0f;
        for (int i = 0; i < NXc; i++) {
            s2   += s2red[i];
            vmax  = fmaxf(vmax, vmred[i]);
        }
        out[NXc] = s2 * (1.0f / 64.0f);   // phi2 = mean(u^2)

        const float vden = fmaxf(vmax, 1e-12f);
        for (int i = 0; i < NXc; i++) {
            float vn = vmred[i] / vden;   // in [0, 1]
            int b = (int)floorf(vn * 64.0f);
            if (b > 63) b = 63;
            if (b < 0)  b = 0;
            // Exact searchsorted(edges, vn, 'right'): edges k/64 exact in fp32.
            while (b > 0  && vn <  (float)b       * (1.0f / 64.0f)) b--;
            while (b < 63 && vn >= (float)(b + 1) * (1.0f / 64.0f)) b++;
            hist[b]++;
        }
        float H = 0.0f;
        for (int i = 0; i < NXc; i++) {
            float pb = (float)hist[i] * (1.0f / 64.0f);
            H -= pb * logf(pb + 1e-12f);
        }
        if (vmax < 1e-12f) H = 0.0f;
        out[NXc + 1] = H;
    }
}

extern "C" void kernel_launch(void* const* d_in, const int* in_sizes, int n_in,
                              void* d_out, int out_size) {
    const float* u0    = (const float*)d_in[0];
    const float* w1    = (const float*)d_in[1];
    const float* b1    = (const float*)d_in[2];
    const float* w2    = (const float*)d_in[3];
    const float* b2    = (const float*)d_in[4];
    const float* wc    = (const float*)d_in[5];
    const float* bc    = (const float*)d_in[6];
    const float* gamma = (const float*)d_in[7];
    const int*   Nt    = (const int*)d_in[8];
    float* out = (float*)d_out;

    scct_kernel<<<1, 256>>>(u0, w1, b1, w2, b2, wc, bc, gamma, Nt, out);
}

// round 17
// speedup vs baseline: 1.1028x; 1.0277x over previous
#include <cuda_runtime.h>

// SCCT_NGT: 5000-step explicit PDE loop on NX=64 with tiny MLP closure,
// then phi2 = mean(u^2) and histogram entropy H of |u|/max.
//
// One persistent CTA, 256 threads = 8 warps (2/SMSP). Thread t: point
// p = t>>2, sub = t&3 owns an 8-unit slice of the 32 hidden units.
//
// R17: ZERO-shfl exchange. u stored as float4 of per-lane partials,
// u = (m0+m1)+(m2+m3). Every lane stores DTg*s_own (lane 0 adds base)
// to fp[sub] — unpredicated, conflict-free STS.32. Consumers read 3x
// LDS.128 (quad-broadcast) and reconstruct with a depth-2 FADD tree.
// vs R15 (714us, one shfl hop): tail -26 (shfl gone), head +4 (tree).
// Lineage: R7 754 (2 hops) -> R15 714 (1 hop) -> R17 (0 hops).

#define NXc 64
#define HIDc 16
#define UPT 8   // hidden units per thread

__device__ __forceinline__ float tanhf_mufu(float x) {
    float y; asm("tanh.approx.f32 %0, %1;" : "=f"(y) : "f"(x)); return y;
}

__global__ __launch_bounds__(256, 1)
void scct_kernel(const float* __restrict__ u0,
                 const float* __restrict__ w1, const float* __restrict__ b1,
                 const float* __restrict__ w2, const float* __restrict__ b2,
                 const float* __restrict__ wc, const float* __restrict__ bc,
                 const float* __restrict__ gammap, const int* __restrict__ Ntp,
                 float* __restrict__ out)
{
    __shared__ float4 ubuf[2][NXc + 2];  // 4 partials; ghosts stay {0,0,0,0}
    __shared__ float s2red[NXc];
    __shared__ float vmred[NXc];
    __shared__ int   hist[NXc];

    const int t   = threadIdx.x;
    const int p   = t >> 2;      // grid point 0..63
    const int sub = t & 3;       // 4 threads per point
    const float bmask = (p == 0 || p == NXc - 1) ? 0.0f : 1.0f;  // Dirichlet
    const float bsel  = (sub == 0) ? 1.0f : 0.0f;  // base only in lane 0's slot

    const float gamma = gammap[0];
    const int   Nt    = Ntp[0];
    const float bcv   = bc[0];

    const float DTf  = (float)1e-4;
    const float R2DX = 31.5f;     // 1/(2*DX), exact
    const float RDX2 = 3969.0f;   // 1/DX^2, exact

    // Masked per-thread update constants (zero on boundary threads -> un = 0).
    const float DTf_m  = DTf * bmask;
    const float DTg_m  = DTf * gamma * bmask;
    const float DTgb_m = DTf * gamma * bcv * bmask;
    const float K08R   = 0.8f * RDX2;        // core: (um+up) coeff
    const float C1     = 0.5f - 2.0f * K08R; // core: uc coeff

    // This thread's 8-unit weight slice, stencil pre-folded:
    //   z_j = um*(RDX2*wq - R2DX*wb) + uc*(wa - 2*RDX2*wq)
    //       + up*(R2DX*wb + RDX2*wq) + bb
    const float* W  = (sub >> 1) ? w2 : w1;
    const float* Bp = (sub >> 1) ? b2 : b1;
    const int j0 = (sub & 1) * UPT;
    float Aw[UPT], Bw[UPT], Cw[UPT], bb[UPT], cwr[UPT];
#pragma unroll
    for (int k = 0; k < UPT; k++) {
        int j = j0 + k;
        float wa = W[j * 3 + 0];
        float wb = W[j * 3 + 1];
        float wq = W[j * 3 + 2];
        Aw[k]  = RDX2 * wq - R2DX * wb;
        Bw[k]  = wa - 2.0f * RDX2 * wq;
        Cw[k]  = R2DX * wb + RDX2 * wq;
        bb[k]  = Bp[j];
        cwr[k] = wc[(sub >> 1) * HIDc + j];
    }

    // Init shared buffers (ghosts zero in both buffers; never rewritten).
    if (t < NXc + 2) {
        ubuf[0][t] = make_float4(0.0f, 0.0f, 0.0f, 0.0f);
        ubuf[1][t] = make_float4(0.0f, 0.0f, 0.0f, 0.0f);
    }
    __syncthreads();
    if (t < NXc) ubuf[0][t + 1].x = u0[t];
    __syncthreads();

    float4* bufA = &ubuf[0][0];
    float4* bufB = &ubuf[1][0];

    for (int it = 0; it < Nt; ++it) {
        const float4 vm = bufA[p];
        const float4 vc = bufA[p + 1];
        const float4 vp = bufA[p + 2];
        const float um = (vm.x + vm.y) + (vm.z + vm.w);
        const float uc = (vc.x + vc.y) + (vc.z + vc.w);
        const float up = (vp.x + vp.y) + (vp.z + vp.w);

        // core = 0.8*lap + 0.5*uc - uc^3 = (um+up)*K08R + uc*(C1 - uc^2)
        const float q    = fmaf(-uc, uc, C1);
        const float core = fmaf(um + up, K08R, uc * q);
        const float base = fmaf(DTf_m, core, uc * bmask) + DTgb_m;

        float s0 = 0.0f, s1 = 0.0f;
#pragma unroll
        for (int k = 0; k < UPT; k += 2) {
            float za = fmaf(up, Cw[k],   fmaf(uc, Bw[k],   fmaf(um, Aw[k],   bb[k])));
            float zb = fmaf(up, Cw[k+1], fmaf(uc, Bw[k+1], fmaf(um, Aw[k+1], bb[k+1])));
            float ta = tanhf_mufu(za);
            float tb = tanhf_mufu(zb);
            s0 = fmaf(cwr[k],   ta, s0);
            s1 = fmaf(cwr[k+1], tb, s1);
        }
        const float s = s0 + s1;

        // Zero-shfl store: every lane writes its own partial (lane 0 + base).
        float* fp = reinterpret_cast<float*>(&bufB[p + 1]);
        fp[sub] = fmaf(DTg_m, s, base * bsel);
        __syncthreads();
        float4* tmp = bufA; bufA = bufB; bufB = tmp;
    }

    // ---- Final statistics ----
    if (t < NXc) {
        float4 vv = bufA[t + 1];
        float v = (vv.x + vv.y) + (vv.z + vv.w);
        out[t]     = v;
        s2red[t]   = v * v;
        vmred[t]   = fabsf(v);
        hist[t]    = 0;
    }
    __syncthreads();

    if (t == 0) {
        float s2 = 0.0f, vmax = 0.0f;
        for (int i = 0; i < NXc; i++) {
            s2   += s2red[i];
            vmax  = fmaxf(vmax, vmred[i]);
        }
        out[NXc] = s2 * (1.0f / 64.0f);   // phi2 = mean(u^2)

        const float vden = fmaxf(vmax, 1e-12f);
        for (int i = 0; i < NXc; i++) {
            float vn = vmred[i] / vden;   // in [0, 1]
            int b = (int)floorf(vn * 64.0f);
            if (b > 63) b = 63;
            if (b < 0)  b = 0;
            // Exact searchsorted(edges, vn, 'right'): edges k/64 exact in fp32.
            while (b > 0  && vn <  (float)b       * (1.0f / 64.0f)) b--;
            while (b < 63 && vn >= (float)(b + 1) * (1.0f / 64.0f)) b++;
            hist[b]++;
        }
        float H = 0.0f;
        for (int i = 0; i < NXc; i++) {
            float pb = (float)hist[i] * (1.0f / 64.0f);
            H -= pb * logf(pb + 1e-12f);
        }
        if (vmax < 1e-12f) H = 0.0f;
        out[NXc + 1] = H;
    }
}

extern "C" void kernel_launch(void* const* d_in, const int* in_sizes, int n_in,
                              void* d_out, int out_size) {
    const float* u0    = (const float*)d_in[0];
    const float* w1    = (const float*)d_in[1];
    const float* b1    = (const float*)d_in[2];
    const float* w2    = (const float*)d_in[3];
    const float* b2    = (const float*)d_in[4];
    const float* wc    = (const float*)d_in[5];
    const float* bc    = (const float*)d_in[6];
    const float* gamma = (const float*)d_in[7];
    const int*   Nt    = (const int*)d_in[8];
    float* out = (float*)d_out;

    scct_kernel<<<1, 256>>>(u0, w1, b1, w2, b2, wc, bc, gamma, Nt, out);
}